// round 1
// baseline (speedup 1.0000x reference)
#include <cuda_runtime.h>

// Problem constants
#define NB 2
#define NS 2048
#define NE 1024
#define NH 16
#define ND 64
#define NM (NB * NS)   // 4096 rows total
#define QS 68          // padded smem row stride (floats)

// Scratch for projected Q/K/V in [B, H, S, D] layout (static device arrays —
// allocation is forbidden, __device__ globals are the sanctioned path).
__device__ float g_q[(size_t)NM * NE];
__device__ float g_k[(size_t)NM * NE];
__device__ float g_v[(size_t)NM * NE];

// ---------------------------------------------------------------------------
// QKV projection: out[b,h,s,d] = sum_k x[m,k] * W[n,k] + bias[n]
// (m = b*S+s, n = h*64+d).  128x128x8 tiling, 8x8 per thread, 256 threads.
// ---------------------------------------------------------------------------
__global__ __launch_bounds__(256) void qkv_gemm_kernel(
    const float* __restrict__ A,
    const float* __restrict__ W,
    const float* __restrict__ bias,
    int which)
{
    __shared__ float As[8][128];
    __shared__ float Bs[8][128];

    float* out = (which == 0) ? g_q : (which == 1) ? g_k : g_v;

    const int tid = threadIdx.x;
    const int bM = blockIdx.y * 128;
    const int bN = blockIdx.x * 128;

    const int lRow = tid >> 1;          // 0..127
    const int lK   = (tid & 1) << 2;    // 0 or 4

    const float* Ap = A + (size_t)(bM + lRow) * NE + lK;
    const float* Wp = W + (size_t)(bN + lRow) * NE + lK;

    const int tr = tid >> 4;            // 0..15
    const int tc = tid & 15;            // 0..15

    float acc[8][8];
#pragma unroll
    for (int i = 0; i < 8; i++)
#pragma unroll
        for (int j = 0; j < 8; j++) acc[i][j] = 0.f;

    for (int k0 = 0; k0 < NE; k0 += 8) {
        float4 a = *(const float4*)(Ap + k0);
        float4 w = *(const float4*)(Wp + k0);
        As[lK + 0][lRow] = a.x;
        As[lK + 1][lRow] = a.y;
        As[lK + 2][lRow] = a.z;
        As[lK + 3][lRow] = a.w;
        Bs[lK + 0][lRow] = w.x;
        Bs[lK + 1][lRow] = w.y;
        Bs[lK + 2][lRow] = w.z;
        Bs[lK + 3][lRow] = w.w;
        __syncthreads();

#pragma unroll
        for (int kk = 0; kk < 8; kk++) {
            float4 m0 = *(const float4*)&As[kk][tr * 8];
            float4 m1 = *(const float4*)&As[kk][tr * 8 + 4];
            float4 n0 = *(const float4*)&Bs[kk][tc * 8];
            float4 n1 = *(const float4*)&Bs[kk][tc * 8 + 4];
            float rm[8] = {m0.x, m0.y, m0.z, m0.w, m1.x, m1.y, m1.z, m1.w};
            float rn[8] = {n0.x, n0.y, n0.z, n0.w, n1.x, n1.y, n1.z, n1.w};
#pragma unroll
            for (int i = 0; i < 8; i++)
#pragma unroll
                for (int j = 0; j < 8; j++)
                    acc[i][j] += rm[i] * rn[j];
        }
        __syncthreads();
    }

    // Epilogue: add bias, scatter to [B, H, S, D]
#pragma unroll
    for (int i = 0; i < 8; i++) {
        int m = bM + tr * 8 + i;
        int bb = m >> 11;           // / 2048
        int s  = m & (NS - 1);
#pragma unroll
        for (int j4 = 0; j4 < 8; j4 += 4) {
            int n = bN + tc * 8 + j4;
            int h = n >> 6;
            int d = n & 63;
            float4 v;
            v.x = acc[i][j4 + 0] + bias[n + 0];
            v.y = acc[i][j4 + 1] + bias[n + 1];
            v.z = acc[i][j4 + 2] + bias[n + 2];
            v.w = acc[i][j4 + 3] + bias[n + 3];
            size_t idx = (((size_t)(bb * NH + h) * NS + s) * ND) + d;
            *(float4*)&out[idx] = v;
        }
    }
}

// ---------------------------------------------------------------------------
// Flash-attention (fp32): one block per (b, h, 64-row q tile).
// 256 threads as 16x16 (tx, ty); thread owns rows {ty+16i} and cols {tx+16j}
// of each 64x64 tile (strided mapping keeps smem conflicts <= 2-way).
// Online softmax state replicated across the 16 tx-lanes of each row group.
// ---------------------------------------------------------------------------
__global__ __launch_bounds__(256) void attn_kernel(
    const int* __restrict__ is_masked_p,
    float* __restrict__ out)
{
    extern __shared__ float sm[];
    float* sQ  = sm;                 // 64 x QS
    float* sKV = sm + 64 * QS;       // 64 x QS (K, then reused for V)
    float* sP  = sm + 2 * 64 * QS;   // 64 x QS

    const int qt  = blockIdx.x;
    const int h   = blockIdx.y;
    const int b   = blockIdx.z;
    const int tid = threadIdx.x;
    const int tx  = tid & 15;
    const int ty  = tid >> 4;

    const size_t head_off = (size_t)(b * NH + h) * NS * ND;
    const float* Qb = g_q + head_off;
    const float* Kb = g_k + head_off;
    const float* Vb = g_v + head_off;

    // Load Q tile (64 x 64)
    for (int i = tid; i < 1024; i += 256) {
        int r = i >> 4;
        int c = (i & 15) << 2;
        *(float4*)&sQ[r * QS + c] =
            *(const float4*)&Qb[(size_t)(qt * 64 + r) * ND + c];
    }

    const bool masked = (*is_masked_p) != 0;
    const int ntiles = masked ? (qt + 1) : (NS / 64);
    const float SCALE = 0.125f;   // 1/sqrt(64)

    float m_i[4], l_i[4], o[4][4];
#pragma unroll
    for (int i = 0; i < 4; i++) {
        m_i[i] = -1e30f;
        l_i[i] = 0.f;
#pragma unroll
        for (int j = 0; j < 4; j++) o[i][j] = 0.f;
    }

    for (int t = 0; t < ntiles; t++) {
        __syncthreads();   // prior iter done with sKV/sP; Q load visible at t=0

        // Load K tile
        for (int i2 = tid; i2 < 1024; i2 += 256) {
            int r = i2 >> 4;
            int c = (i2 & 15) << 2;
            *(float4*)&sKV[r * QS + c] =
                *(const float4*)&Kb[(size_t)(t * 64 + r) * ND + c];
        }
        __syncthreads();

        // S = Q K^T (each thread: 4x4 dots over d = 64)
        float s[4][4];
#pragma unroll
        for (int i = 0; i < 4; i++)
#pragma unroll
            for (int j = 0; j < 4; j++) s[i][j] = 0.f;

#pragma unroll 4
        for (int d4 = 0; d4 < 64; d4 += 4) {
            float4 qv[4], kv[4];
#pragma unroll
            for (int i = 0; i < 4; i++)
                qv[i] = *(const float4*)&sQ[(ty + 16 * i) * QS + d4];
#pragma unroll
            for (int j = 0; j < 4; j++)
                kv[j] = *(const float4*)&sKV[(tx + 16 * j) * QS + d4];
#pragma unroll
            for (int i = 0; i < 4; i++)
#pragma unroll
                for (int j = 0; j < 4; j++)
                    s[i][j] += qv[i].x * kv[j].x + qv[i].y * kv[j].y +
                               qv[i].z * kv[j].z + qv[i].w * kv[j].w;
        }

        const bool diag = masked && (t == qt);

        // Scale, mask, row max (reduce across the 16 tx-lanes)
        float rmax[4];
#pragma unroll
        for (int i = 0; i < 4; i++) {
            float mx = -1e30f;
#pragma unroll
            for (int j = 0; j < 4; j++) {
                s[i][j] *= SCALE;
                if (diag && (tx + 16 * j) > (ty + 16 * i)) s[i][j] = -1e9f;
                mx = fmaxf(mx, s[i][j]);
            }
#pragma unroll
            for (int off = 8; off > 0; off >>= 1)
                mx = fmaxf(mx, __shfl_xor_sync(0xffffffffu, mx, off));
            rmax[i] = mx;
        }

        // Online softmax update; write P to smem
#pragma unroll
        for (int i = 0; i < 4; i++) {
            float mnew = fmaxf(m_i[i], rmax[i]);
            float corr = __expf(m_i[i] - mnew);
            float rs = 0.f;
#pragma unroll
            for (int j = 0; j < 4; j++) {
                float p = __expf(s[i][j] - mnew);
                sP[(ty + 16 * i) * QS + tx + 16 * j] = p;
                rs += p;
            }
#pragma unroll
            for (int off = 8; off > 0; off >>= 1)
                rs += __shfl_xor_sync(0xffffffffu, rs, off);
            l_i[i] = l_i[i] * corr + rs;
            m_i[i] = mnew;
#pragma unroll
            for (int j = 0; j < 4; j++) o[i][j] *= corr;
        }
        __syncthreads();   // K reads + P writes complete

        // Load V tile into sKV
        for (int i2 = tid; i2 < 1024; i2 += 256) {
            int r = i2 >> 4;
            int c = (i2 & 15) << 2;
            *(float4*)&sKV[r * QS + c] =
                *(const float4*)&Vb[(size_t)(t * 64 + r) * ND + c];
        }
        __syncthreads();

        // O += P @ V
#pragma unroll 4
        for (int c4 = 0; c4 < 64; c4 += 4) {
            float4 pv[4];
#pragma unroll
            for (int i = 0; i < 4; i++)
                pv[i] = *(const float4*)&sP[(ty + 16 * i) * QS + c4];
#pragma unroll
            for (int cc = 0; cc < 4; cc++) {
                float vr[4];
#pragma unroll
                for (int j = 0; j < 4; j++)
                    vr[j] = sKV[(c4 + cc) * QS + tx + 16 * j];
#pragma unroll
                for (int i = 0; i < 4; i++) {
                    float pc = ((const float*)&pv[i])[cc];
#pragma unroll
                    for (int j = 0; j < 4; j++)
                        o[i][j] += pc * vr[j];
                }
            }
        }
    }

    // Epilogue: normalize, write out[b, s, h*64 + d]
#pragma unroll
    for (int i = 0; i < 4; i++) {
        float inv = 1.f / l_i[i];
        int r = qt * 64 + ty + 16 * i;
        size_t base = ((size_t)b * NS + r) * NE + h * ND;
#pragma unroll
        for (int j = 0; j < 4; j++)
            out[base + tx + 16 * j] = o[i][j] * inv;
    }
}

// ---------------------------------------------------------------------------
extern "C" void kernel_launch(void* const* d_in, const int* in_sizes, int n_in,
                              void* d_out, int out_size)
{
    const float* x     = (const float*)d_in[0];
    const float* Wq_w  = (const float*)d_in[1];
    const float* Wq_b  = (const float*)d_in[2];
    const float* Wk_w  = (const float*)d_in[3];
    const float* Wk_b  = (const float*)d_in[4];
    const float* Wv_w  = (const float*)d_in[5];
    const float* Wv_b  = (const float*)d_in[6];
    const int*   is_masked = (const int*)d_in[7];
    float* out = (float*)d_out;

    (void)in_sizes; (void)n_in; (void)out_size;

    const int attn_smem = 3 * 64 * QS * sizeof(float);  // 52224 B
    cudaFuncSetAttribute(attn_kernel,
                         cudaFuncAttributeMaxDynamicSharedMemorySize,
                         attn_smem);

    dim3 gg(NE / 128, NM / 128);   // (8, 32)
    qkv_gemm_kernel<<<gg, 256>>>(x, Wq_w, Wq_b, 0);
    qkv_gemm_kernel<<<gg, 256>>>(x, Wk_w, Wk_b, 1);
    qkv_gemm_kernel<<<gg, 256>>>(x, Wv_w, Wv_b, 2);

    dim3 ga(NS / 64, NH, NB);      // (32, 16, 2)
    attn_kernel<<<ga, 256, attn_smem>>>(is_masked, out);
}

// round 3
// speedup vs baseline: 1.5294x; 1.5294x over previous
#include <cuda_runtime.h>
#include <cstdint>

// Problem constants
#define NB 2
#define NS 2048
#define NE 1024
#define NH 16
#define ND 64
#define NM (NB * NS)   // 4096 rows
#define QS 68          // padded smem row stride (floats) for attention

// ---------------------------------------------------------------------------
// Static device scratch (allocation is forbidden; __device__ globals are the
// sanctioned path).
// ---------------------------------------------------------------------------
__device__ __align__(16) float g_xr[(size_t)NM * NE];        // tf32-rounded x
__device__ __align__(16) float g_wr[3][(size_t)NE * NE];     // tf32-rounded W
__device__ float g_q[(size_t)NM * NE];
__device__ float g_k[(size_t)NM * NE];
__device__ float g_v[(size_t)NM * NE];

// ---------------------------------------------------------------------------
// Helpers
// ---------------------------------------------------------------------------
__device__ __forceinline__ uint32_t smem_u32(const void* p) {
    uint32_t a;
    asm("{ .reg .u64 t; cvta.to.shared.u64 t, %1; cvt.u32.u64 %0, t; }"
        : "=r"(a) : "l"(p));
    return a;
}

__device__ __forceinline__ void cp_async16(uint32_t dst, const void* src) {
    asm volatile("cp.async.cg.shared.global [%0], [%1], 16;"
                 :: "r"(dst), "l"(src) : "memory");
}
#define CP_COMMIT() asm volatile("cp.async.commit_group;" ::: "memory")
#define CP_WAIT(n)  asm volatile("cp.async.wait_group %0;" :: "n"(n) : "memory")

__device__ __forceinline__ float rna_tf32(float v) {
    uint32_t r;
    asm("cvt.rna.tf32.f32 %0, %1;" : "=r"(r) : "f"(v));
    return __uint_as_float(r);
}

// m16n8k8 tf32 mma: D = A*B + D
__device__ __forceinline__ void mma_tf32(float* c, const float* a,
                                         float b0, float b1) {
    asm volatile(
        "mma.sync.aligned.m16n8k8.row.col.f32.tf32.tf32.f32 "
        "{%0,%1,%2,%3}, {%4,%5,%6,%7}, {%8,%9}, {%0,%1,%2,%3};"
        : "+f"(c[0]), "+f"(c[1]), "+f"(c[2]), "+f"(c[3])
        : "r"(__float_as_uint(a[0])), "r"(__float_as_uint(a[1])),
          "r"(__float_as_uint(a[2])), "r"(__float_as_uint(a[3])),
          "r"(__float_as_uint(b0)),  "r"(__float_as_uint(b1)));
}

// ---------------------------------------------------------------------------
// tf32 rounding pre-pass
// ---------------------------------------------------------------------------
__global__ __launch_bounds__(256) void tf32_round_kernel(
    const float4* __restrict__ src, float4* __restrict__ dst, int n4)
{
    int i = blockIdx.x * 256 + threadIdx.x;
    if (i >= n4) return;
    float4 v = src[i];
    v.x = rna_tf32(v.x); v.y = rna_tf32(v.y);
    v.z = rna_tf32(v.z); v.w = rna_tf32(v.w);
    dst[i] = v;
}

// ---------------------------------------------------------------------------
// QKV projection via mma.sync tf32.
// out[b,h,s,d] = sum_k xr[m,k] * wr[n,k] + bias[n]   (NT GEMM, both K-major)
// Block tile 128x128, K-step 32, cp.async double buffer.
// 8 warps: warpM = wid&3 (32 rows each), warpN = wid>>2 (64 cols each).
// Warp tile 32x64 = 2 m-tiles x 8 n-tiles of m16n8.
// Smem: [row][36] fp32 (pad 36 => conflict-free fragment reads, 16B-aligned
// row starts for cp.async).
// ---------------------------------------------------------------------------
#define KSTEP 32
#define RPAD 36
#define TILE_ELEMS (128 * RPAD)                 // floats per operand per stage
#define PROJ_SMEM (2 * 2 * TILE_ELEMS * 4)      // 147456 B? no: 2 stages*2 ops
// 2 stages * 2 operands * 18432 B = 73728 B
#undef PROJ_SMEM
#define PROJ_SMEM (2 * 2 * TILE_ELEMS * (int)sizeof(float))

__global__ __launch_bounds__(256) void proj_mma_kernel(
    const float* __restrict__ A,       // [NM][NE] tf32-rounded x
    const float* __restrict__ W,       // [NE][NE] tf32-rounded weight
    const float* __restrict__ bias,
    float* __restrict__ out)
{
    extern __shared__ __align__(16) float sm[];
    // layout: stage0 A | stage0 B | stage1 A | stage1 B
    float* sA[2] = {sm, sm + 2 * TILE_ELEMS};
    float* sB[2] = {sm + TILE_ELEMS, sm + 3 * TILE_ELEMS};
    const uint32_t smb = smem_u32(sm);

    const int tid = threadIdx.x;
    const int wid = tid >> 5;
    const int lane = tid & 31;
    const int g  = lane >> 2;   // 0..7
    const int tg = lane & 3;    // 0..3
    const int warpM = wid & 3;
    const int warpN = wid >> 2;
    const int bM = blockIdx.y * 128;
    const int bN = blockIdx.x * 128;

    // Per-thread copy assignment: 4 float4 chunks per operand per stage.
    // chunk c (0..1023): row = c>>3, kq = c&7  (8 x 16B chunks per 32-float row)
    auto load_stage = [&](int stage, int k0) {
        uint32_t dA = smb + (uint32_t)((stage * 2) * TILE_ELEMS) * 4;
        uint32_t dB = smb + (uint32_t)((stage * 2 + 1) * TILE_ELEMS) * 4;
#pragma unroll
        for (int i = 0; i < 4; i++) {
            int c = tid + 256 * i;
            int row = c >> 3;
            int kq = (c & 7) << 2;
            uint32_t doff = (uint32_t)(row * RPAD + kq) * 4;
            cp_async16(dA + doff, &A[(size_t)(bM + row) * NE + k0 + kq]);
            cp_async16(dB + doff, &W[(size_t)(bN + row) * NE + k0 + kq]);
        }
        CP_COMMIT();
    };

    float acc[2][8][4];
#pragma unroll
    for (int mt = 0; mt < 2; mt++)
#pragma unroll
        for (int nt = 0; nt < 8; nt++)
#pragma unroll
            for (int r = 0; r < 4; r++) acc[mt][nt][r] = 0.f;

    load_stage(0, 0);

    const int NKT = NE / KSTEP;    // 32
    for (int kt = 0; kt < NKT; kt++) {
        int st = kt & 1;
        if (kt + 1 < NKT) {
            load_stage(st ^ 1, (kt + 1) * KSTEP);
            CP_WAIT(1);
        } else {
            CP_WAIT(0);
        }
        __syncthreads();

        const float* a_s = sA[st];
        const float* b_s = sB[st];
        const int ra0 = warpM * 32 + g;          // m-tile 0, row +0
        const int rb0 = warpN * 64 + g;

#pragma unroll
        for (int k8 = 0; k8 < 4; k8++) {
            const int kc = k8 * 8 + tg;
            float a[2][4];
#pragma unroll
            for (int mt = 0; mt < 2; mt++) {
                int r0 = ra0 + mt * 16;
                a[mt][0] = a_s[r0 * RPAD + kc];
                a[mt][1] = a_s[(r0 + 8) * RPAD + kc];
                a[mt][2] = a_s[r0 * RPAD + kc + 4];
                a[mt][3] = a_s[(r0 + 8) * RPAD + kc + 4];
            }
#pragma unroll
            for (int nt = 0; nt < 8; nt++) {
                int rn = rb0 + nt * 8 - g + g;   // warpN*64 + nt*8 + g
                float b0 = b_s[(warpN * 64 + nt * 8 + g) * RPAD + kc];
                float b1 = b_s[(warpN * 64 + nt * 8 + g) * RPAD + kc + 4];
                (void)rn;
                mma_tf32(acc[0][nt], a[0], b0, b1);
                mma_tf32(acc[1][nt], a[1], b0, b1);
            }
        }
        __syncthreads();   // all warps done with this stage before overwrite
    }

    // Epilogue: add bias, scatter to [B, H, S, D]
#pragma unroll
    for (int mt = 0; mt < 2; mt++) {
        int r0 = bM + warpM * 32 + mt * 16 + g;
#pragma unroll
        for (int half = 0; half < 2; half++) {
            int m = r0 + 8 * half;
            int bb = m >> 11;
            int s = m & (NS - 1);
#pragma unroll
            for (int nt = 0; nt < 8; nt++) {
                int n = bN + warpN * 64 + nt * 8 + 2 * tg;
                int h = n >> 6;
                int d = n & 63;
                float2 v;
                v.x = acc[mt][nt][2 * half + 0] + bias[n + 0];
                v.y = acc[mt][nt][2 * half + 1] + bias[n + 1];
                size_t idx = (((size_t)(bb * NH + h) * NS + s) * ND) + d;
                *(float2*)&out[idx] = v;
            }
        }
    }
}

// ---------------------------------------------------------------------------
// Flash-attention (fp32) — unchanged from round 1 (known good).
// ---------------------------------------------------------------------------
__global__ __launch_bounds__(256) void attn_kernel(
    const int* __restrict__ is_masked_p,
    float* __restrict__ out)
{
    extern __shared__ float sm[];
    float* sQ  = sm;
    float* sKV = sm + 64 * QS;
    float* sP  = sm + 2 * 64 * QS;

    const int qt  = blockIdx.x;
    const int h   = blockIdx.y;
    const int b   = blockIdx.z;
    const int tid = threadIdx.x;
    const int tx  = tid & 15;
    const int ty  = tid >> 4;

    const size_t head_off = (size_t)(b * NH + h) * NS * ND;
    const float* Qb = g_q + head_off;
    const float* Kb = g_k + head_off;
    const float* Vb = g_v + head_off;

    for (int i = tid; i < 1024; i += 256) {
        int r = i >> 4;
        int c = (i & 15) << 2;
        *(float4*)&sQ[r * QS + c] =
            *(const float4*)&Qb[(size_t)(qt * 64 + r) * ND + c];
    }

    const bool masked = (*is_masked_p) != 0;
    const int ntiles = masked ? (qt + 1) : (NS / 64);
    const float SCALE = 0.125f;

    float m_i[4], l_i[4], o[4][4];
#pragma unroll
    for (int i = 0; i < 4; i++) {
        m_i[i] = -1e30f;
        l_i[i] = 0.f;
#pragma unroll
        for (int j = 0; j < 4; j++) o[i][j] = 0.f;
    }

    for (int t = 0; t < ntiles; t++) {
        __syncthreads();

        for (int i2 = tid; i2 < 1024; i2 += 256) {
            int r = i2 >> 4;
            int c = (i2 & 15) << 2;
            *(float4*)&sKV[r * QS + c] =
                *(const float4*)&Kb[(size_t)(t * 64 + r) * ND + c];
        }
        __syncthreads();

        float s[4][4];
#pragma unroll
        for (int i = 0; i < 4; i++)
#pragma unroll
            for (int j = 0; j < 4; j++) s[i][j] = 0.f;

#pragma unroll 4
        for (int d4 = 0; d4 < 64; d4 += 4) {
            float4 qv[4], kv[4];
#pragma unroll
            for (int i = 0; i < 4; i++)
                qv[i] = *(const float4*)&sQ[(ty + 16 * i) * QS + d4];
#pragma unroll
            for (int j = 0; j < 4; j++)
                kv[j] = *(const float4*)&sKV[(tx + 16 * j) * QS + d4];
#pragma unroll
            for (int i = 0; i < 4; i++)
#pragma unroll
                for (int j = 0; j < 4; j++)
                    s[i][j] += qv[i].x * kv[j].x + qv[i].y * kv[j].y +
                               qv[i].z * kv[j].z + qv[i].w * kv[j].w;
        }

        const bool diag = masked && (t == qt);

        float rmax[4];
#pragma unroll
        for (int i = 0; i < 4; i++) {
            float mx = -1e30f;
#pragma unroll
            for (int j = 0; j < 4; j++) {
                s[i][j] *= SCALE;
                if (diag && (tx + 16 * j) > (ty + 16 * i)) s[i][j] = -1e9f;
                mx = fmaxf(mx, s[i][j]);
            }
#pragma unroll
            for (int off = 8; off > 0; off >>= 1)
                mx = fmaxf(mx, __shfl_xor_sync(0xffffffffu, mx, off));
            rmax[i] = mx;
        }

#pragma unroll
        for (int i = 0; i < 4; i++) {
            float mnew = fmaxf(m_i[i], rmax[i]);
            float corr = __expf(m_i[i] - mnew);
            float rs = 0.f;
#pragma unroll
            for (int j = 0; j < 4; j++) {
                float p = __expf(s[i][j] - mnew);
                sP[(ty + 16 * i) * QS + tx + 16 * j] = p;
                rs += p;
            }
#pragma unroll
            for (int off = 8; off > 0; off >>= 1)
                rs += __shfl_xor_sync(0xffffffffu, rs, off);
            l_i[i] = l_i[i] * corr + rs;
            m_i[i] = mnew;
#pragma unroll
            for (int j = 0; j < 4; j++) o[i][j] *= corr;
        }
        __syncthreads();

        for (int i2 = tid; i2 < 1024; i2 += 256) {
            int r = i2 >> 4;
            int c = (i2 & 15) << 2;
            *(float4*)&sKV[r * QS + c] =
                *(const float4*)&Vb[(size_t)(t * 64 + r) * ND + c];
        }
        __syncthreads();

#pragma unroll 4
        for (int c4 = 0; c4 < 64; c4 += 4) {
            float4 pv[4];
#pragma unroll
            for (int i = 0; i < 4; i++)
                pv[i] = *(const float4*)&sP[(ty + 16 * i) * QS + c4];
#pragma unroll
            for (int cc = 0; cc < 4; cc++) {
                float vr[4];
#pragma unroll
                for (int j = 0; j < 4; j++)
                    vr[j] = sKV[(c4 + cc) * QS + tx + 16 * j];
#pragma unroll
                for (int i = 0; i < 4; i++) {
                    float pc = ((const float*)&pv[i])[cc];
#pragma unroll
                    for (int j = 0; j < 4; j++)
                        o[i][j] += pc * vr[j];
                }
            }
        }
    }

#pragma unroll
    for (int i = 0; i < 4; i++) {
        float inv = 1.f / l_i[i];
        int r = qt * 64 + ty + 16 * i;
        size_t base = ((size_t)b * NS + r) * NE + h * ND;
#pragma unroll
        for (int j = 0; j < 4; j++)
            out[base + tx + 16 * j] = o[i][j] * inv;
    }
}

// ---------------------------------------------------------------------------
// Host
// ---------------------------------------------------------------------------
extern "C" void kernel_launch(void* const* d_in, const int* in_sizes, int n_in,
                              void* d_out, int out_size)
{
    const float* x     = (const float*)d_in[0];
    const float* Wq_w  = (const float*)d_in[1];
    const float* Wq_b  = (const float*)d_in[2];
    const float* Wk_w  = (const float*)d_in[3];
    const float* Wk_b  = (const float*)d_in[4];
    const float* Wv_w  = (const float*)d_in[5];
    const float* Wv_b  = (const float*)d_in[6];
    const int*   is_masked = (const int*)d_in[7];
    float* out = (float*)d_out;
    (void)in_sizes; (void)n_in; (void)out_size;

    void *p_xr, *p_wr, *p_q, *p_k, *p_v;
    cudaGetSymbolAddress(&p_xr, g_xr);
    cudaGetSymbolAddress(&p_wr, g_wr);
    cudaGetSymbolAddress(&p_q, g_q);
    cudaGetSymbolAddress(&p_k, g_k);
    cudaGetSymbolAddress(&p_v, g_v);
    float* wr0 = (float*)p_wr;
    float* wr1 = wr0 + (size_t)NE * NE;
    float* wr2 = wr1 + (size_t)NE * NE;

    // Unbiased tf32 pre-rounding
    int n4x = NM * NE / 4;
    int n4w = NE * NE / 4;
    tf32_round_kernel<<<(n4x + 255) / 256, 256>>>((const float4*)x, (float4*)p_xr, n4x);
    tf32_round_kernel<<<(n4w + 255) / 256, 256>>>((const float4*)Wq_w, (float4*)wr0, n4w);
    tf32_round_kernel<<<(n4w + 255) / 256, 256>>>((const float4*)Wk_w, (float4*)wr1, n4w);
    tf32_round_kernel<<<(n4w + 255) / 256, 256>>>((const float4*)Wv_w, (float4*)wr2, n4w);

    cudaFuncSetAttribute(proj_mma_kernel,
                         cudaFuncAttributeMaxDynamicSharedMemorySize, PROJ_SMEM);
    const int attn_smem = 3 * 64 * QS * sizeof(float);
    cudaFuncSetAttribute(attn_kernel,
                         cudaFuncAttributeMaxDynamicSharedMemorySize, attn_smem);

    dim3 gg(NE / 128, NM / 128);   // (8, 32)
    proj_mma_kernel<<<gg, 256, PROJ_SMEM>>>((const float*)p_xr, wr0, Wq_b, (float*)p_q);
    proj_mma_kernel<<<gg, 256, PROJ_SMEM>>>((const float*)p_xr, wr1, Wk_b, (float*)p_k);
    proj_mma_kernel<<<gg, 256, PROJ_SMEM>>>((const float*)p_xr, wr2, Wv_b, (float*)p_v);

    dim3 ga(NS / 64, NH, NB);      // (32, 16, 2)
    attn_kernel<<<ga, 256, attn_smem>>>(is_masked, out);
}

// round 4
// speedup vs baseline: 2.3836x; 1.5585x over previous
#include <cuda_runtime.h>
#include <cstdint>

// Problem constants
#define NB 2
#define NS 2048
#define NE 1024
#define NH 16
#define ND 64
#define NM (NB * NS)   // 4096 rows

// ---------------------------------------------------------------------------
// Static device scratch
// ---------------------------------------------------------------------------
__device__ __align__(16) float g_xr[(size_t)NM * NE];        // tf32-rounded x
__device__ __align__(16) float g_wr[3][(size_t)NE * NE];     // tf32-rounded W
__device__ float g_q[(size_t)NM * NE];
__device__ float g_k[(size_t)NM * NE];
__device__ float g_v[(size_t)NM * NE];

// ---------------------------------------------------------------------------
// Helpers
// ---------------------------------------------------------------------------
__device__ __forceinline__ uint32_t smem_u32(const void* p) {
    uint32_t a;
    asm("{ .reg .u64 t; cvta.to.shared.u64 t, %1; cvt.u32.u64 %0, t; }"
        : "=r"(a) : "l"(p));
    return a;
}

__device__ __forceinline__ void cp_async16(uint32_t dst, const void* src) {
    asm volatile("cp.async.cg.shared.global [%0], [%1], 16;"
                 :: "r"(dst), "l"(src) : "memory");
}
#define CP_COMMIT() asm volatile("cp.async.commit_group;" ::: "memory")
#define CP_WAIT(n)  asm volatile("cp.async.wait_group %0;" :: "n"(n) : "memory")

__device__ __forceinline__ float rna_tf32(float v) {
    uint32_t r;
    asm("cvt.rna.tf32.f32 %0, %1;" : "=r"(r) : "f"(v));
    return __uint_as_float(r);
}

// m16n8k8 tf32 mma: D = A*B + D
__device__ __forceinline__ void mma_tf32(float* c, const float* a,
                                         float b0, float b1) {
    asm volatile(
        "mma.sync.aligned.m16n8k8.row.col.f32.tf32.tf32.f32 "
        "{%0,%1,%2,%3}, {%4,%5,%6,%7}, {%8,%9}, {%0,%1,%2,%3};"
        : "+f"(c[0]), "+f"(c[1]), "+f"(c[2]), "+f"(c[3])
        : "r"(__float_as_uint(a[0])), "r"(__float_as_uint(a[1])),
          "r"(__float_as_uint(a[2])), "r"(__float_as_uint(a[3])),
          "r"(__float_as_uint(b0)),  "r"(__float_as_uint(b1)));
}

// Fast exp via FMA (no MUFU): rint range reduction + deg-4 poly for 2^f.
// Rel err < 1e-5 on the softmax domain (arg <= 0).
__device__ __forceinline__ float fexp(float x) {
    x = fmaxf(x, -87.0f);
    float z = x * 1.4426950408889634f;
    float r = rintf(z);
    float f = z - r;
    float p = 0.0096181291f;
    p = fmaf(p, f, 0.0555041087f);
    p = fmaf(p, f, 0.2402265070f);
    p = fmaf(p, f, 0.6931471806f);
    p = fmaf(p, f, 1.0f);
    int e = (int)r;
    return p * __int_as_float((e + 127) << 23);
}

// ---------------------------------------------------------------------------
// tf32 rounding pre-pass
// ---------------------------------------------------------------------------
__global__ __launch_bounds__(256) void tf32_round_kernel(
    const float4* __restrict__ src, float4* __restrict__ dst, int n4)
{
    int i = blockIdx.x * 256 + threadIdx.x;
    if (i >= n4) return;
    float4 v = src[i];
    v.x = rna_tf32(v.x); v.y = rna_tf32(v.y);
    v.z = rna_tf32(v.z); v.w = rna_tf32(v.w);
    dst[i] = v;
}

// ---------------------------------------------------------------------------
// QKV projection via mma.sync tf32 (unchanged from round 3, known good).
// ---------------------------------------------------------------------------
#define KSTEP 32
#define RPAD 36
#define TILE_ELEMS (128 * RPAD)
#define PROJ_SMEM (2 * 2 * TILE_ELEMS * (int)sizeof(float))

__global__ __launch_bounds__(256) void proj_mma_kernel(
    const float* __restrict__ A,
    const float* __restrict__ W,
    const float* __restrict__ bias,
    float* __restrict__ out)
{
    extern __shared__ __align__(16) float sm[];
    float* sA[2] = {sm, sm + 2 * TILE_ELEMS};
    float* sB[2] = {sm + TILE_ELEMS, sm + 3 * TILE_ELEMS};
    const uint32_t smb = smem_u32(sm);

    const int tid = threadIdx.x;
    const int wid = tid >> 5;
    const int lane = tid & 31;
    const int g  = lane >> 2;
    const int tg = lane & 3;
    const int warpM = wid & 3;
    const int warpN = wid >> 2;
    const int bM = blockIdx.y * 128;
    const int bN = blockIdx.x * 128;

    auto load_stage = [&](int stage, int k0) {
        uint32_t dA = smb + (uint32_t)((stage * 2) * TILE_ELEMS) * 4;
        uint32_t dB = smb + (uint32_t)((stage * 2 + 1) * TILE_ELEMS) * 4;
#pragma unroll
        for (int i = 0; i < 4; i++) {
            int c = tid + 256 * i;
            int row = c >> 3;
            int kq = (c & 7) << 2;
            uint32_t doff = (uint32_t)(row * RPAD + kq) * 4;
            cp_async16(dA + doff, &A[(size_t)(bM + row) * NE + k0 + kq]);
            cp_async16(dB + doff, &W[(size_t)(bN + row) * NE + k0 + kq]);
        }
        CP_COMMIT();
    };

    float acc[2][8][4];
#pragma unroll
    for (int mt = 0; mt < 2; mt++)
#pragma unroll
        for (int nt = 0; nt < 8; nt++)
#pragma unroll
            for (int r = 0; r < 4; r++) acc[mt][nt][r] = 0.f;

    load_stage(0, 0);

    const int NKT = NE / KSTEP;
    for (int kt = 0; kt < NKT; kt++) {
        int st = kt & 1;
        if (kt + 1 < NKT) {
            load_stage(st ^ 1, (kt + 1) * KSTEP);
            CP_WAIT(1);
        } else {
            CP_WAIT(0);
        }
        __syncthreads();

        const float* a_s = sA[st];
        const float* b_s = sB[st];
        const int ra0 = warpM * 32 + g;

#pragma unroll
        for (int k8 = 0; k8 < 4; k8++) {
            const int kc = k8 * 8 + tg;
            float a[2][4];
#pragma unroll
            for (int mt = 0; mt < 2; mt++) {
                int r0 = ra0 + mt * 16;
                a[mt][0] = a_s[r0 * RPAD + kc];
                a[mt][1] = a_s[(r0 + 8) * RPAD + kc];
                a[mt][2] = a_s[r0 * RPAD + kc + 4];
                a[mt][3] = a_s[(r0 + 8) * RPAD + kc + 4];
            }
#pragma unroll
            for (int nt = 0; nt < 8; nt++) {
                float b0 = b_s[(warpN * 64 + nt * 8 + g) * RPAD + kc];
                float b1 = b_s[(warpN * 64 + nt * 8 + g) * RPAD + kc + 4];
                mma_tf32(acc[0][nt], a[0], b0, b1);
                mma_tf32(acc[1][nt], a[1], b0, b1);
            }
        }
        __syncthreads();
    }

#pragma unroll
    for (int mt = 0; mt < 2; mt++) {
        int r0 = bM + warpM * 32 + mt * 16 + g;
#pragma unroll
        for (int half = 0; half < 2; half++) {
            int m = r0 + 8 * half;
            int bb = m >> 11;
            int s = m & (NS - 1);
#pragma unroll
            for (int nt = 0; nt < 8; nt++) {
                int n = bN + warpN * 64 + nt * 8 + 2 * tg;
                int h = n >> 6;
                int d = n & 63;
                float2 v;
                v.x = acc[mt][nt][2 * half + 0] + bias[n + 0];
                v.y = acc[mt][nt][2 * half + 1] + bias[n + 1];
                size_t idx = (((size_t)(bb * NH + h) * NS + s) * ND) + d;
                *(float2*)&out[idx] = v;
            }
        }
    }
}

// ---------------------------------------------------------------------------
// Tensor-core flash attention (tf32 mma.sync).
// Block = (qtile of 64 rows, h, b); 4 warps, warp owns 16 q-rows.
// Per KV tile (64): S = Q K^T via mma; online softmax in accumulator layout
// (quad shfl reductions); P staged via warp-private smem; O += P V^T via mma
// with V transposed at load.
// ---------------------------------------------------------------------------
#define AST 68   // smem row stride (68 mod 32 == 4 -> conflict-free frags)
#define ATTN_SMEM (4 * 64 * AST * (int)sizeof(float))   // 69632 B

__global__ __launch_bounds__(128) void attn_mma_kernel(
    const int* __restrict__ is_masked_p,
    float* __restrict__ out)
{
    extern __shared__ __align__(16) float smx[];
    float* sQ  = smx;
    float* sK  = smx + 64 * AST;
    float* sVt = smx + 2 * 64 * AST;
    float* sP  = smx + 3 * 64 * AST;

    const int qt = blockIdx.x, h = blockIdx.y, b = blockIdx.z;
    const int tid = threadIdx.x;
    const int wid = tid >> 5, lane = tid & 31;
    const int g = lane >> 2, tg = lane & 3;
    const int m0 = wid * 16;
    const float SCALE = 0.125f;   // 1/sqrt(64)

    const size_t head = (size_t)(b * NH + h) * NS * ND;
    const float* Qb = g_q + head;
    const float* Kb = g_k + head;
    const float* Vb = g_v + head;

    // Load Q tile (rna -> tf32)
#pragma unroll
    for (int i = 0; i < 8; i++) {
        int c = tid + 128 * i;
        int r = c >> 4, c4 = (c & 15) << 2;
        float4 v = *(const float4*)&Qb[(size_t)(qt * 64 + r) * ND + c4];
        v.x = rna_tf32(v.x); v.y = rna_tf32(v.y);
        v.z = rna_tf32(v.z); v.w = rna_tf32(v.w);
        *(float4*)&sQ[r * AST + c4] = v;
    }
    __syncthreads();

    // Hoist Q fragments into registers (reused every KV tile)
    float aQ[8][4];
#pragma unroll
    for (int k8 = 0; k8 < 8; k8++) {
        int kc = k8 * 8 + tg;
        aQ[k8][0] = sQ[(m0 + g) * AST + kc];
        aQ[k8][1] = sQ[(m0 + g + 8) * AST + kc];
        aQ[k8][2] = sQ[(m0 + g) * AST + kc + 4];
        aQ[k8][3] = sQ[(m0 + g + 8) * AST + kc + 4];
    }

    const bool masked = (*is_masked_p) != 0;
    const int ntiles = masked ? (qt + 1) : (NS / 64);

    float mrow0 = -1e30f, mrow1 = -1e30f;
    float lrow0 = 0.f, lrow1 = 0.f;
    float o[8][4];
#pragma unroll
    for (int nt = 0; nt < 8; nt++)
#pragma unroll
        for (int r = 0; r < 4; r++) o[nt][r] = 0.f;

    const int rg0 = qt * 64 + m0 + g;
    const int rg1 = rg0 + 8;

    for (int t = 0; t < ntiles; t++) {
        __syncthreads();   // everyone done with previous sK/sVt

        // K tile (row = kv pos, col = d), rna -> tf32
#pragma unroll
        for (int i = 0; i < 8; i++) {
            int c = tid + 128 * i;
            int r = c >> 4, c4 = (c & 15) << 2;
            float4 v = *(const float4*)&Kb[(size_t)(t * 64 + r) * ND + c4];
            v.x = rna_tf32(v.x); v.y = rna_tf32(v.y);
            v.z = rna_tf32(v.z); v.w = rna_tf32(v.w);
            *(float4*)&sK[r * AST + c4] = v;
        }
        // V tile transposed: sVt[d][k] = V[t*64+k][d], rna -> tf32
#pragma unroll
        for (int i = 0; i < 8; i++) {
            int c = tid + 128 * i;
            int k = c & 63, dq = (c >> 6) << 2;
            float4 v = *(const float4*)&Vb[(size_t)(t * 64 + k) * ND + dq];
            sVt[(dq + 0) * AST + k] = rna_tf32(v.x);
            sVt[(dq + 1) * AST + k] = rna_tf32(v.y);
            sVt[(dq + 2) * AST + k] = rna_tf32(v.z);
            sVt[(dq + 3) * AST + k] = rna_tf32(v.w);
        }
        __syncthreads();

        // S = Q K^T
        float s[8][4];
#pragma unroll
        for (int nt = 0; nt < 8; nt++)
#pragma unroll
            for (int r = 0; r < 4; r++) s[nt][r] = 0.f;

#pragma unroll
        for (int k8 = 0; k8 < 8; k8++) {
            int kc = k8 * 8 + tg;
#pragma unroll
            for (int nt = 0; nt < 8; nt++) {
                float b0 = sK[(nt * 8 + g) * AST + kc];
                float b1 = sK[(nt * 8 + g) * AST + kc + 4];
                mma_tf32(s[nt], aQ[k8], b0, b1);
            }
        }

        // Scale + causal mask + row max
        const bool diag = masked && (t == qt);
        float mx0 = -1e30f, mx1 = -1e30f;
#pragma unroll
        for (int nt = 0; nt < 8; nt++) {
            int cg = t * 64 + nt * 8 + 2 * tg;
            s[nt][0] *= SCALE; s[nt][1] *= SCALE;
            s[nt][2] *= SCALE; s[nt][3] *= SCALE;
            if (diag) {
                if (cg > rg0)     s[nt][0] = -1e9f;
                if (cg + 1 > rg0) s[nt][1] = -1e9f;
                if (cg > rg1)     s[nt][2] = -1e9f;
                if (cg + 1 > rg1) s[nt][3] = -1e9f;
            }
            mx0 = fmaxf(mx0, fmaxf(s[nt][0], s[nt][1]));
            mx1 = fmaxf(mx1, fmaxf(s[nt][2], s[nt][3]));
        }
        mx0 = fmaxf(mx0, __shfl_xor_sync(0xffffffffu, mx0, 1));
        mx0 = fmaxf(mx0, __shfl_xor_sync(0xffffffffu, mx0, 2));
        mx1 = fmaxf(mx1, __shfl_xor_sync(0xffffffffu, mx1, 1));
        mx1 = fmaxf(mx1, __shfl_xor_sync(0xffffffffu, mx1, 2));

        float mn0 = fmaxf(mrow0, mx0), mn1 = fmaxf(mrow1, mx1);
        float corr0 = fexp(mrow0 - mn0), corr1 = fexp(mrow1 - mn1);

        // P = exp(S - m), rna-rounded so l-sum and PV mma agree; stage in smem
        float rs0 = 0.f, rs1 = 0.f;
#pragma unroll
        for (int nt = 0; nt < 8; nt++) {
            float p0 = rna_tf32(fexp(s[nt][0] - mn0));
            float p1 = rna_tf32(fexp(s[nt][1] - mn0));
            float p2 = rna_tf32(fexp(s[nt][2] - mn1));
            float p3 = rna_tf32(fexp(s[nt][3] - mn1));
            rs0 += p0 + p1;
            rs1 += p2 + p3;
            int cc = nt * 8 + 2 * tg;
            *(float2*)&sP[(m0 + g) * AST + cc]     = make_float2(p0, p1);
            *(float2*)&sP[(m0 + g + 8) * AST + cc] = make_float2(p2, p3);
        }
        rs0 += __shfl_xor_sync(0xffffffffu, rs0, 1);
        rs0 += __shfl_xor_sync(0xffffffffu, rs0, 2);
        rs1 += __shfl_xor_sync(0xffffffffu, rs1, 1);
        rs1 += __shfl_xor_sync(0xffffffffu, rs1, 2);

        lrow0 = lrow0 * corr0 + rs0;
        lrow1 = lrow1 * corr1 + rs1;
        mrow0 = mn0; mrow1 = mn1;
#pragma unroll
        for (int nt = 0; nt < 8; nt++) {
            o[nt][0] *= corr0; o[nt][1] *= corr0;
            o[nt][2] *= corr1; o[nt][3] *= corr1;
        }
        __syncwarp();   // sP rows are warp-private: warp-level ordering suffices

        // O += P V  (A = P from smem, B = Vt col-major)
#pragma unroll
        for (int k8 = 0; k8 < 8; k8++) {
            int kc = k8 * 8 + tg;
            float aP[4];
            aP[0] = sP[(m0 + g) * AST + kc];
            aP[1] = sP[(m0 + g + 8) * AST + kc];
            aP[2] = sP[(m0 + g) * AST + kc + 4];
            aP[3] = sP[(m0 + g + 8) * AST + kc + 4];
#pragma unroll
            for (int nt = 0; nt < 8; nt++) {
                float b0 = sVt[(nt * 8 + g) * AST + kc];
                float b1 = sVt[(nt * 8 + g) * AST + kc + 4];
                mma_tf32(o[nt], aP, b0, b1);
            }
        }
    }

    // Epilogue: normalize, write out[b, s, h*64 + d]
    float inv0 = 1.f / lrow0, inv1 = 1.f / lrow1;
    size_t base0 = ((size_t)b * NS + rg0) * NE + h * ND;
    size_t base1 = ((size_t)b * NS + rg1) * NE + h * ND;
#pragma unroll
    for (int nt = 0; nt < 8; nt++) {
        int cc = nt * 8 + 2 * tg;
        *(float2*)&out[base0 + cc] = make_float2(o[nt][0] * inv0, o[nt][1] * inv0);
        *(float2*)&out[base1 + cc] = make_float2(o[nt][2] * inv1, o[nt][3] * inv1);
    }
}

// ---------------------------------------------------------------------------
// Host
// ---------------------------------------------------------------------------
extern "C" void kernel_launch(void* const* d_in, const int* in_sizes, int n_in,
                              void* d_out, int out_size)
{
    const float* x     = (const float*)d_in[0];
    const float* Wq_w  = (const float*)d_in[1];
    const float* Wq_b  = (const float*)d_in[2];
    const float* Wk_w  = (const float*)d_in[3];
    const float* Wk_b  = (const float*)d_in[4];
    const float* Wv_w  = (const float*)d_in[5];
    const float* Wv_b  = (const float*)d_in[6];
    const int*   is_masked = (const int*)d_in[7];
    float* out = (float*)d_out;
    (void)in_sizes; (void)n_in; (void)out_size;

    void *p_xr, *p_wr, *p_q, *p_k, *p_v;
    cudaGetSymbolAddress(&p_xr, g_xr);
    cudaGetSymbolAddress(&p_wr, g_wr);
    cudaGetSymbolAddress(&p_q, g_q);
    cudaGetSymbolAddress(&p_k, g_k);
    cudaGetSymbolAddress(&p_v, g_v);
    float* wr0 = (float*)p_wr;
    float* wr1 = wr0 + (size_t)NE * NE;
    float* wr2 = wr1 + (size_t)NE * NE;

    int n4x = NM * NE / 4;
    int n4w = NE * NE / 4;
    tf32_round_kernel<<<(n4x + 255) / 256, 256>>>((const float4*)x, (float4*)p_xr, n4x);
    tf32_round_kernel<<<(n4w + 255) / 256, 256>>>((const float4*)Wq_w, (float4*)wr0, n4w);
    tf32_round_kernel<<<(n4w + 255) / 256, 256>>>((const float4*)Wk_w, (float4*)wr1, n4w);
    tf32_round_kernel<<<(n4w + 255) / 256, 256>>>((const float4*)Wv_w, (float4*)wr2, n4w);

    cudaFuncSetAttribute(proj_mma_kernel,
                         cudaFuncAttributeMaxDynamicSharedMemorySize, PROJ_SMEM);
    cudaFuncSetAttribute(attn_mma_kernel,
                         cudaFuncAttributeMaxDynamicSharedMemorySize, ATTN_SMEM);

    dim3 gg(NE / 128, NM / 128);   // (8, 32)
    proj_mma_kernel<<<gg, 256, PROJ_SMEM>>>((const float*)p_xr, wr0, Wq_b, (float*)p_q);
    proj_mma_kernel<<<gg, 256, PROJ_SMEM>>>((const float*)p_xr, wr1, Wk_b, (float*)p_k);
    proj_mma_kernel<<<gg, 256, PROJ_SMEM>>>((const float*)p_xr, wr2, Wv_b, (float*)p_v);

    dim3 ga(NS / 64, NH, NB);      // (32, 16, 2)
    attn_mma_kernel<<<ga, 128, ATTN_SMEM>>>(is_masked, out);
}

// round 5
// speedup vs baseline: 2.7083x; 1.1363x over previous
#include <cuda_runtime.h>
#include <cstdint>

// Problem constants
#define NB 2
#define NS 2048
#define NE 1024
#define NH 16
#define ND 64
#define NM (NB * NS)   // 4096 rows

// ---------------------------------------------------------------------------
// Static device scratch
// ---------------------------------------------------------------------------
__device__ __align__(16) float g_xr[(size_t)NM * NE];        // tf32-rounded x
__device__ __align__(16) float g_wr[3][(size_t)NE * NE];     // tf32-rounded W
__device__ __align__(16) float g_q[(size_t)NM * NE];         // tf32-rounded Q
__device__ __align__(16) float g_k[(size_t)NM * NE];         // tf32-rounded K
__device__ __align__(16) float g_v[(size_t)NM * NE];         // tf32-rounded V

// ---------------------------------------------------------------------------
// Helpers
// ---------------------------------------------------------------------------
__device__ __forceinline__ uint32_t smem_u32(const void* p) {
    uint32_t a;
    asm("{ .reg .u64 t; cvta.to.shared.u64 t, %1; cvt.u32.u64 %0, t; }"
        : "=r"(a) : "l"(p));
    return a;
}

__device__ __forceinline__ void cp_async16(uint32_t dst, const void* src) {
    asm volatile("cp.async.cg.shared.global [%0], [%1], 16;"
                 :: "r"(dst), "l"(src) : "memory");
}
#define CP_COMMIT() asm volatile("cp.async.commit_group;" ::: "memory")
#define CP_WAIT(n)  asm volatile("cp.async.wait_group %0;" :: "n"(n) : "memory")

__device__ __forceinline__ float rna_tf32(float v) {
    uint32_t r;
    asm("cvt.rna.tf32.f32 %0, %1;" : "=r"(r) : "f"(v));
    return __uint_as_float(r);
}

// m16n8k8 tf32 mma: D = A*B + D
__device__ __forceinline__ void mma_tf32(float* c, const float* a,
                                         float b0, float b1) {
    asm volatile(
        "mma.sync.aligned.m16n8k8.row.col.f32.tf32.tf32.f32 "
        "{%0,%1,%2,%3}, {%4,%5,%6,%7}, {%8,%9}, {%0,%1,%2,%3};"
        : "+f"(c[0]), "+f"(c[1]), "+f"(c[2]), "+f"(c[3])
        : "r"(__float_as_uint(a[0])), "r"(__float_as_uint(a[1])),
          "r"(__float_as_uint(a[2])), "r"(__float_as_uint(a[3])),
          "r"(__float_as_uint(b0)),  "r"(__float_as_uint(b1)));
}

// Fast exp via FMA (no MUFU): rint range reduction + deg-4 poly for 2^f.
__device__ __forceinline__ float fexp(float x) {
    x = fmaxf(x, -87.0f);
    float z = x * 1.4426950408889634f;
    float r = rintf(z);
    float f = z - r;
    float p = 0.0096181291f;
    p = fmaf(p, f, 0.0555041087f);
    p = fmaf(p, f, 0.2402265070f);
    p = fmaf(p, f, 0.6931471806f);
    p = fmaf(p, f, 1.0f);
    int e = (int)r;
    return p * __int_as_float((e + 127) << 23);
}

// ---------------------------------------------------------------------------
// tf32 rounding pre-pass
// ---------------------------------------------------------------------------
__global__ __launch_bounds__(256) void tf32_round_kernel(
    const float4* __restrict__ src, float4* __restrict__ dst, int n4)
{
    int i = blockIdx.x * 256 + threadIdx.x;
    if (i >= n4) return;
    float4 v = src[i];
    v.x = rna_tf32(v.x); v.y = rna_tf32(v.y);
    v.z = rna_tf32(v.z); v.w = rna_tf32(v.w);
    dst[i] = v;
}

// ---------------------------------------------------------------------------
// Fused QKV projection via mma.sync tf32: blockIdx.z in {0,1,2} selects
// which of Q/K/V this block computes. Output is rna-rounded to tf32 so the
// attention kernel can cp.async it with no conversion.
// ---------------------------------------------------------------------------
#define KSTEP 32
#define RPAD 36
#define TILE_ELEMS (128 * RPAD)
#define PROJ_SMEM (2 * 2 * TILE_ELEMS * (int)sizeof(float))

__global__ __launch_bounds__(256) void proj_mma_kernel(
    const float* __restrict__ A,
    const float* __restrict__ Wall,        // g_wr base: 3 contiguous weights
    const float* __restrict__ b0p,
    const float* __restrict__ b1p,
    const float* __restrict__ b2p,
    float* __restrict__ q_out,
    float* __restrict__ k_out,
    float* __restrict__ v_out)
{
    extern __shared__ __align__(16) float sm[];
    float* sA[2] = {sm, sm + 2 * TILE_ELEMS};
    float* sB[2] = {sm + TILE_ELEMS, sm + 3 * TILE_ELEMS};
    const uint32_t smb = smem_u32(sm);

    const int z = blockIdx.z;
    const float* W = Wall + (size_t)z * NE * NE;
    const float* bias = (z == 0) ? b0p : (z == 1) ? b1p : b2p;
    float* out = (z == 0) ? q_out : (z == 1) ? k_out : v_out;

    const int tid = threadIdx.x;
    const int wid = tid >> 5;
    const int lane = tid & 31;
    const int g  = lane >> 2;
    const int tg = lane & 3;
    const int warpM = wid & 3;
    const int warpN = wid >> 2;
    const int bM = blockIdx.y * 128;
    const int bN = blockIdx.x * 128;

    auto load_stage = [&](int stage, int k0) {
        uint32_t dA = smb + (uint32_t)((stage * 2) * TILE_ELEMS) * 4;
        uint32_t dB = smb + (uint32_t)((stage * 2 + 1) * TILE_ELEMS) * 4;
#pragma unroll
        for (int i = 0; i < 4; i++) {
            int c = tid + 256 * i;
            int row = c >> 3;
            int kq = (c & 7) << 2;
            uint32_t doff = (uint32_t)(row * RPAD + kq) * 4;
            cp_async16(dA + doff, &A[(size_t)(bM + row) * NE + k0 + kq]);
            cp_async16(dB + doff, &W[(size_t)(bN + row) * NE + k0 + kq]);
        }
        CP_COMMIT();
    };

    float acc[2][8][4];
#pragma unroll
    for (int mt = 0; mt < 2; mt++)
#pragma unroll
        for (int nt = 0; nt < 8; nt++)
#pragma unroll
            for (int r = 0; r < 4; r++) acc[mt][nt][r] = 0.f;

    load_stage(0, 0);

    const int NKT = NE / KSTEP;
    for (int kt = 0; kt < NKT; kt++) {
        int st = kt & 1;
        if (kt + 1 < NKT) {
            load_stage(st ^ 1, (kt + 1) * KSTEP);
            CP_WAIT(1);
        } else {
            CP_WAIT(0);
        }
        __syncthreads();

        const float* a_s = sA[st];
        const float* b_s = sB[st];
        const int ra0 = warpM * 32 + g;

#pragma unroll
        for (int k8 = 0; k8 < 4; k8++) {
            const int kc = k8 * 8 + tg;
            float a[2][4];
#pragma unroll
            for (int mt = 0; mt < 2; mt++) {
                int r0 = ra0 + mt * 16;
                a[mt][0] = a_s[r0 * RPAD + kc];
                a[mt][1] = a_s[(r0 + 8) * RPAD + kc];
                a[mt][2] = a_s[r0 * RPAD + kc + 4];
                a[mt][3] = a_s[(r0 + 8) * RPAD + kc + 4];
            }
#pragma unroll
            for (int nt = 0; nt < 8; nt++) {
                float b0 = b_s[(warpN * 64 + nt * 8 + g) * RPAD + kc];
                float b1 = b_s[(warpN * 64 + nt * 8 + g) * RPAD + kc + 4];
                mma_tf32(acc[0][nt], a[0], b0, b1);
                mma_tf32(acc[1][nt], a[1], b0, b1);
            }
        }
        __syncthreads();
    }

    // Epilogue: bias + rna(tf32) + scatter to [B, H, S, D]
#pragma unroll
    for (int mt = 0; mt < 2; mt++) {
        int r0 = bM + warpM * 32 + mt * 16 + g;
#pragma unroll
        for (int half = 0; half < 2; half++) {
            int m = r0 + 8 * half;
            int bb = m >> 11;
            int s = m & (NS - 1);
#pragma unroll
            for (int nt = 0; nt < 8; nt++) {
                int n = bN + warpN * 64 + nt * 8 + 2 * tg;
                int h = n >> 6;
                int d = n & 63;
                float2 v;
                v.x = rna_tf32(acc[mt][nt][2 * half + 0] + bias[n + 0]);
                v.y = rna_tf32(acc[mt][nt][2 * half + 1] + bias[n + 1]);
                size_t idx = (((size_t)(bb * NH + h) * NS + s) * ND) + d;
                *(float2*)&out[idx] = v;
            }
        }
    }
}

// ---------------------------------------------------------------------------
// Tensor-core flash attention, cp.async double-buffered K/V.
// Block = (64-row qtile, h, b); 4 warps, warp owns 16 q-rows.
// Smem strides: AST=68 for Q/K/P (g-row-indexed reads conflict-free),
// VST=72 for V (k-row-indexed reads conflict-free; 72 mod 32 == 8).
// ---------------------------------------------------------------------------
#define AST 68
#define VST 72
// floats: Q 64*68 | K0 64*68 | K1 64*68 | V0 64*72 | V1 64*72 | P 64*68
#define OFF_Q  0
#define OFF_K0 (64 * AST)
#define OFF_K1 (2 * 64 * AST)
#define OFF_V0 (3 * 64 * AST)
#define OFF_V1 (3 * 64 * AST + 64 * VST)
#define OFF_P  (3 * 64 * AST + 2 * 64 * VST)
#define ATTN_FLOATS (4 * 64 * AST + 2 * 64 * VST)
#define ATTN_SMEM (ATTN_FLOATS * (int)sizeof(float))   // 106496 B

__global__ __launch_bounds__(128) void attn_mma_kernel(
    const int* __restrict__ is_masked_p,
    float* __restrict__ out)
{
    extern __shared__ __align__(16) float smx[];
    const uint32_t smb = smem_u32(smx);
    float* sK[2] = {smx + OFF_K0, smx + OFF_K1};
    float* sV[2] = {smx + OFF_V0, smx + OFF_V1};
    float* sQ = smx + OFF_Q;
    float* sP = smx + OFF_P;

    const int qt = blockIdx.x, h = blockIdx.y, b = blockIdx.z;
    const int tid = threadIdx.x;
    const int wid = tid >> 5, lane = tid & 31;
    const int g = lane >> 2, tg = lane & 3;
    const int m0 = wid * 16;
    const float SCALE = 0.125f;   // 1/sqrt(64)

    const size_t head = (size_t)(b * NH + h) * NS * ND;
    const float* Qb = g_q + head;
    const float* Kb = g_k + head;
    const float* Vb = g_v + head;

    const bool masked = (*is_masked_p) != 0;
    const int ntiles = masked ? (qt + 1) : (NS / 64);

    // Prefetch: tile t -> stage t&1. K rows stride AST, V rows stride VST.
    auto prefetch = [&](int t) {
        int st = t & 1;
        uint32_t dK = smb + (uint32_t)(st ? OFF_K1 : OFF_K0) * 4;
        uint32_t dV = smb + (uint32_t)(st ? OFF_V1 : OFF_V0) * 4;
#pragma unroll
        for (int i = 0; i < 8; i++) {
            int c = tid + 128 * i;
            int r = c >> 4, c4 = (c & 15) << 2;
            const float* src = &Kb[(size_t)(t * 64 + r) * ND + c4];
            cp_async16(dK + (uint32_t)(r * AST + c4) * 4, src);
            const float* srcv = &Vb[(size_t)(t * 64 + r) * ND + c4];
            cp_async16(dV + (uint32_t)(r * VST + c4) * 4, srcv);
        }
        CP_COMMIT();
    };

    // Group 0: Q tile + tile 0
    {
        uint32_t dQ = smb + (uint32_t)OFF_Q * 4;
#pragma unroll
        for (int i = 0; i < 8; i++) {
            int c = tid + 128 * i;
            int r = c >> 4, c4 = (c & 15) << 2;
            cp_async16(dQ + (uint32_t)(r * AST + c4) * 4,
                       &Qb[(size_t)(qt * 64 + r) * ND + c4]);
        }
    }
    prefetch(0);   // commits Q + tile0 together

    float aQ[8][4];
    float mrow0 = -1e30f, mrow1 = -1e30f;
    float lrow0 = 0.f, lrow1 = 0.f;
    float o[8][4];
#pragma unroll
    for (int nt = 0; nt < 8; nt++)
#pragma unroll
        for (int r = 0; r < 4; r++) o[nt][r] = 0.f;

    const int rg0 = qt * 64 + m0 + g;
    const int rg1 = rg0 + 8;

    for (int t = 0; t < ntiles; t++) {
        const int st = t & 1;
        if (t + 1 < ntiles) {
            prefetch(t + 1);
            CP_WAIT(1);
        } else {
            CP_WAIT(0);
        }
        __syncthreads();

        if (t == 0) {
            // Hoist Q fragments (reused every tile)
#pragma unroll
            for (int k8 = 0; k8 < 8; k8++) {
                int kc = k8 * 8 + tg;
                aQ[k8][0] = sQ[(m0 + g) * AST + kc];
                aQ[k8][1] = sQ[(m0 + g + 8) * AST + kc];
                aQ[k8][2] = sQ[(m0 + g) * AST + kc + 4];
                aQ[k8][3] = sQ[(m0 + g + 8) * AST + kc + 4];
            }
        }

        // S = Q K^T
        float s[8][4];
#pragma unroll
        for (int nt = 0; nt < 8; nt++)
#pragma unroll
            for (int r = 0; r < 4; r++) s[nt][r] = 0.f;

        const float* k_s = sK[st];
#pragma unroll
        for (int k8 = 0; k8 < 8; k8++) {
            int kc = k8 * 8 + tg;
#pragma unroll
            for (int nt = 0; nt < 8; nt++) {
                float b0 = k_s[(nt * 8 + g) * AST + kc];
                float b1 = k_s[(nt * 8 + g) * AST + kc + 4];
                mma_tf32(s[nt], aQ[k8], b0, b1);
            }
        }

        // Scale + causal mask + row max (quad reduction)
        const bool diag = masked && (t == qt);
        float mx0 = -1e30f, mx1 = -1e30f;
#pragma unroll
        for (int nt = 0; nt < 8; nt++) {
            int cg = t * 64 + nt * 8 + 2 * tg;
            s[nt][0] *= SCALE; s[nt][1] *= SCALE;
            s[nt][2] *= SCALE; s[nt][3] *= SCALE;
            if (diag) {
                if (cg > rg0)     s[nt][0] = -1e9f;
                if (cg + 1 > rg0) s[nt][1] = -1e9f;
                if (cg > rg1)     s[nt][2] = -1e9f;
                if (cg + 1 > rg1) s[nt][3] = -1e9f;
            }
            mx0 = fmaxf(mx0, fmaxf(s[nt][0], s[nt][1]));
            mx1 = fmaxf(mx1, fmaxf(s[nt][2], s[nt][3]));
        }
        mx0 = fmaxf(mx0, __shfl_xor_sync(0xffffffffu, mx0, 1));
        mx0 = fmaxf(mx0, __shfl_xor_sync(0xffffffffu, mx0, 2));
        mx1 = fmaxf(mx1, __shfl_xor_sync(0xffffffffu, mx1, 1));
        mx1 = fmaxf(mx1, __shfl_xor_sync(0xffffffffu, mx1, 2));

        float mn0 = fmaxf(mrow0, mx0), mn1 = fmaxf(mrow1, mx1);
        float corr0 = fexp(mrow0 - mn0), corr1 = fexp(mrow1 - mn1);

        // P = rna(exp(S - m)); stage via warp-private smem rows
        float rs0 = 0.f, rs1 = 0.f;
#pragma unroll
        for (int nt = 0; nt < 8; nt++) {
            float p0 = rna_tf32(fexp(s[nt][0] - mn0));
            float p1 = rna_tf32(fexp(s[nt][1] - mn0));
            float p2 = rna_tf32(fexp(s[nt][2] - mn1));
            float p3 = rna_tf32(fexp(s[nt][3] - mn1));
            rs0 += p0 + p1;
            rs1 += p2 + p3;
            int cc = nt * 8 + 2 * tg;
            *(float2*)&sP[(m0 + g) * AST + cc]     = make_float2(p0, p1);
            *(float2*)&sP[(m0 + g + 8) * AST + cc] = make_float2(p2, p3);
        }
        rs0 += __shfl_xor_sync(0xffffffffu, rs0, 1);
        rs0 += __shfl_xor_sync(0xffffffffu, rs0, 2);
        rs1 += __shfl_xor_sync(0xffffffffu, rs1, 1);
        rs1 += __shfl_xor_sync(0xffffffffu, rs1, 2);

        lrow0 = lrow0 * corr0 + rs0;
        lrow1 = lrow1 * corr1 + rs1;
        mrow0 = mn0; mrow1 = mn1;
#pragma unroll
        for (int nt = 0; nt < 8; nt++) {
            o[nt][0] *= corr0; o[nt][1] *= corr0;
            o[nt][2] *= corr1; o[nt][3] *= corr1;
        }
        __syncwarp();

        // O += P V   (B from V[k][d] directly: b = sV[kc*VST + n])
        const float* v_s = sV[st];
#pragma unroll
        for (int k8 = 0; k8 < 8; k8++) {
            int kc = k8 * 8 + tg;
            float aP[4];
            aP[0] = sP[(m0 + g) * AST + kc];
            aP[1] = sP[(m0 + g + 8) * AST + kc];
            aP[2] = sP[(m0 + g) * AST + kc + 4];
            aP[3] = sP[(m0 + g + 8) * AST + kc + 4];
#pragma unroll
            for (int nt = 0; nt < 8; nt++) {
                int n = nt * 8 + g;
                float b0 = v_s[kc * VST + n];
                float b1 = v_s[(kc + 4) * VST + n];
                mma_tf32(o[nt], aP, b0, b1);
            }
        }
        __syncthreads();   // stage buffer free for prefetch of t+2
    }

    // Epilogue: normalize, write out[b, s, h*64 + d]
    float inv0 = 1.f / lrow0, inv1 = 1.f / lrow1;
    size_t base0 = ((size_t)b * NS + rg0) * NE + h * ND;
    size_t base1 = ((size_t)b * NS + rg1) * NE + h * ND;
#pragma unroll
    for (int nt = 0; nt < 8; nt++) {
        int cc = nt * 8 + 2 * tg;
        *(float2*)&out[base0 + cc] = make_float2(o[nt][0] * inv0, o[nt][1] * inv0);
        *(float2*)&out[base1 + cc] = make_float2(o[nt][2] * inv1, o[nt][3] * inv1);
    }
}

// ---------------------------------------------------------------------------
// Host
// ---------------------------------------------------------------------------
extern "C" void kernel_launch(void* const* d_in, const int* in_sizes, int n_in,
                              void* d_out, int out_size)
{
    const float* x     = (const float*)d_in[0];
    const float* Wq_w  = (const float*)d_in[1];
    const float* Wq_b  = (const float*)d_in[2];
    const float* Wk_w  = (const float*)d_in[3];
    const float* Wk_b  = (const float*)d_in[4];
    const float* Wv_w  = (const float*)d_in[5];
    const float* Wv_b  = (const float*)d_in[6];
    const int*   is_masked = (const int*)d_in[7];
    float* out = (float*)d_out;
    (void)in_sizes; (void)n_in; (void)out_size;

    void *p_xr, *p_wr, *p_q, *p_k, *p_v;
    cudaGetSymbolAddress(&p_xr, g_xr);
    cudaGetSymbolAddress(&p_wr, g_wr);
    cudaGetSymbolAddress(&p_q, g_q);
    cudaGetSymbolAddress(&p_k, g_k);
    cudaGetSymbolAddress(&p_v, g_v);
    float* wr0 = (float*)p_wr;
    float* wr1 = wr0 + (size_t)NE * NE;
    float* wr2 = wr1 + (size_t)NE * NE;

    int n4x = NM * NE / 4;
    int n4w = NE * NE / 4;
    tf32_round_kernel<<<(n4x + 255) / 256, 256>>>((const float4*)x, (float4*)p_xr, n4x);
    tf32_round_kernel<<<(n4w + 255) / 256, 256>>>((const float4*)Wq_w, (float4*)wr0, n4w);
    tf32_round_kernel<<<(n4w + 255) / 256, 256>>>((const float4*)Wk_w, (float4*)wr1, n4w);
    tf32_round_kernel<<<(n4w + 255) / 256, 256>>>((const float4*)Wv_w, (float4*)wr2, n4w);

    cudaFuncSetAttribute(proj_mma_kernel,
                         cudaFuncAttributeMaxDynamicSharedMemorySize, PROJ_SMEM);
    cudaFuncSetAttribute(attn_mma_kernel,
                         cudaFuncAttributeMaxDynamicSharedMemorySize, ATTN_SMEM);

    dim3 gg(NE / 128, NM / 128, 3);   // (8, 32, 3) — fused Q/K/V
    proj_mma_kernel<<<gg, 256, PROJ_SMEM>>>((const float*)p_xr, wr0,
                                            Wq_b, Wk_b, Wv_b,
                                            (float*)p_q, (float*)p_k, (float*)p_v);

    dim3 ga(NS / 64, NH, NB);         // (32, 16, 2)
    attn_mma_kernel<<<ga, 128, ATTN_SMEM>>>(is_masked, out);
}